// round 12
// baseline (speedup 1.0000x reference)
#include <cuda_runtime.h>
#include <cstdint>

// Problem constants
#define NM      31
#define NPLANE  (NM*NM)        // 961
#define NK      (NM*NM*NM)     // 29791
#define NB      8
#define NPTS    3000
#define NCH     4
#define NBW     12
#define NXH     16             // half-space planes nx = 0..15
#define NSPLIT  4
#define JCHUNK  (NPTS/NSPLIT)  // 750
#define PCHUNK  32             // particles per pipeline stage
#define NCHUNK  ((JCHUNK + PCHUNK - 1)/PCHUNK)   // 24
#define TWO_PI_L 0.628318530717958647692f
#define HALF_L   5.0f
#define INV2V    (1.0f/2000.0f)

typedef unsigned long long u64;

// Padded F tensor: [b][ixh][c][iy:32][z:32], zero-padded at iy=31 / z=31
#define FPAD    (NB*NXH*NCH*32*32)     // 524288 float2 = 4.2 MB

// Scratch (static device globals; allocation-free per harness rules)
__device__ __align__(256) float2 g_Exy[NB*NPTS*NXH*32];  // [pidx][ixh][i], 98.3 MB
__device__ __align__(256) float2 g_Ez2[NB*NPTS*32];      // [pidx][i], 6.1 MB
__device__ __align__(256) float2 g_E3[NB*NPTS*3*32];     // [pidx][dim][i], 18.4 MB
__device__ float2 g_Fp[NSPLIT*NB*NCH*NXH*NPLANE];        // partial structure factors
__device__ float2 g_F2[FPAD];                            // mult(+w)-folded, padded
__device__ float  g_mult[NK];
__device__ float  g_diag;

__device__ __forceinline__ float2 cmul(float2 a, float2 b) {
    return make_float2(a.x*b.x - a.y*b.y, a.x*b.y + a.y*b.x);
}
__device__ __forceinline__ u64 pk(float x, float y) {
    u64 r; asm("mov.b64 %0,{%1,%2};" : "=l"(r) : "f"(x), "f"(y)); return r;
}
__device__ __forceinline__ float2 upk(u64 v) {
    float2 f; asm("mov.b64 {%0,%1},%2;" : "=f"(f.x), "=f"(f.y) : "l"(v)); return f;
}
__device__ __forceinline__ u64 swap64(u64 v) {
    float2 f = upk(v); return pk(f.y, f.x);
}
__device__ __forceinline__ u64 ffma2(u64 a, u64 b, u64 c) {
    u64 d; asm("fma.rn.f32x2 %0,%1,%2,%3;" : "=l"(d) : "l"(a), "l"(b), "l"(c)); return d;
}
__device__ __forceinline__ u64 fmul2(u64 a, u64 b) {
    u64 d; asm("mul.rn.f32x2 %0,%1,%2;" : "=l"(d) : "l"(a), "l"(b)); return d;
}
__device__ __forceinline__ uint32_t smem_u32(const void* p) {
    return static_cast<uint32_t>(__cvta_generic_to_shared(p));
}
__device__ __forceinline__ void cp16(uint32_t dst, const void* src, int srcsz) {
    asm volatile("cp.async.cg.shared.global [%0],[%1],16,%2;"
                 :: "r"(dst), "l"(src), "r"(srcsz));
}
__device__ __forceinline__ void cp_commit() {
    asm volatile("cp.async.commit_group;");
}
template<int N> __device__ __forceinline__ void cp_wait() {
    asm volatile("cp.async.wait_group %0;" :: "n"(N));
}

// ---------------------------------------------------------------------------
// 1) mult(k)
// ---------------------------------------------------------------------------
__global__ void mult_kernel(const float* __restrict__ shift,
                            const float* __restrict__ amp) {
    int i = blockIdx.x * blockDim.x + threadIdx.x;
    if (i >= NK) return;
    int ix = i / NPLANE;
    int r  = i - ix * NPLANE;
    int iy = r / NM;
    int iz = r - iy * NM;
    float kx = TWO_PI_L * (float)(ix - 15);
    float ky = TWO_PI_L * (float)(iy - 15);
    float kz = TWO_PI_L * (float)(iz - 15);
    float k2 = kx*kx + ky*ky + kz*kz;
    float m = 0.0f;
#pragma unroll
    for (int b = 0; b < NBW; b++) {
        m += amp[b] * __expf(-k2 * __expf(2.0f * shift[b]));
    }
    if (k2 == 0.0f) m = 0.0f;
    g_mult[i] = m;
}

// ---------------------------------------------------------------------------
// 2) diag_sum
// ---------------------------------------------------------------------------
__global__ void diag_kernel() {
    __shared__ float sh[1024];
    int tid = threadIdx.x;
    float s = 0.0f;
    for (int i = tid; i < NK; i += 1024) s += g_mult[i];
    sh[tid] = s;
    __syncthreads();
    for (int o = 512; o > 0; o >>= 1) {
        if (tid < o) sh[tid] += sh[tid + o];
        __syncthreads();
    }
    if (tid == 0) g_diag = sh[0] * INV2V;
}

// ---------------------------------------------------------------------------
// 3) E tables: one warp per particle, coalesced 256B row stores.
//    Emits: g_Exy (scatter), g_Ez2 (scatter/gather), g_E3 (gather ex/ey/ez).
// ---------------------------------------------------------------------------
__global__ void etab_kernel(const float* __restrict__ pos) {
    int gw   = (blockIdx.x * blockDim.x + threadIdx.x) >> 5;  // particle
    int lane = threadIdx.x & 31;
    if (gw >= NB * NPTS) return;

    float tx = TWO_PI_L * (pos[gw*3 + 0] - HALF_L);
    float ty = TWO_PI_L * (pos[gw*3 + 1] - HALF_L);
    float tz = TWO_PI_L * (pos[gw*3 + 2] - HALF_L);

    float n = (float)(lane - 15);
    float sy, cy, sz, cz;
    sincosf(n * ty, &sy, &cy);
    sincosf(n * tz, &sz, &cz);
    bool valid = (lane < NM);
    float2 ey = valid ? make_float2(cy, -sy) : make_float2(0.f, 0.f);
    float2 ez = valid ? make_float2(cz, -sz) : make_float2(0.f, 0.f);

    g_Ez2[gw*32 + lane] = ez;
    g_E3[(gw*3 + 1)*32 + lane] = ey;
    g_E3[(gw*3 + 2)*32 + lane] = ez;

    float sx, cx;
    sincosf(tx, &sx, &cx);
    float2 e1x = make_float2(cx, -sx);
    float2 ex  = make_float2(1.f, 0.f);
    float2* row = &g_Exy[gw * (NXH*32)];
#pragma unroll
    for (int it = 0; it < NXH; it++) {
        if (lane == 0) g_E3[(gw*3 + 0)*32 + 15 + it] = ex;  // Ex[nx=it]
        row[it*32 + lane] = cmul(ex, ey);
        ex = cmul(ex, e1x);
    }
}

// ---------------------------------------------------------------------------
// 4) Scatter (r7 form, best measured 278 us). 128-thread CTA per
//    (ixh, b, split); thread tile (2 iy) x (4 z) x (4 ch). Double-buffered
//    cp.async staging.
// ---------------------------------------------------------------------------
__global__ void __launch_bounds__(128, 4) scatter_kernel(const float* __restrict__ charge) {
    const int ixh   = blockIdx.x;        // 0..15
    const int b     = blockIdx.y;
    const int split = blockIdx.z;
    const int tid   = threadIdx.x;
    const int iy0   = (tid >> 3) * 2;    // 0,2,..,30
    const int z0    = (tid & 7) * 4;     // 0,4,..,28
    const int jstart = split * JCHUNK;
    const int jend   = jstart + JCHUNK;

    __shared__ __align__(128) float2 sXY[2][PCHUNK][32];   // raw exy   2x8 KB
    __shared__ __align__(128) float2 sEz[2][PCHUNK][32];   //           2x8 KB
    __shared__ __align__(128) float4 sQ [2][PCHUNK];       //           2x0.5 KB

    auto stage = [&](int cn, int bf) {
        int j0 = jstart + cn * PCHUNK;
        for (int idx = tid; idx < 1056; idx += 128) {
            if (idx < 512) {
                int p = idx >> 4, o = (idx & 15) * 2;
                int j = j0 + p;
                int js = (j < jend) ? j : jstart;
                int sz = (j < jend) ? 16 : 0;
                cp16(smem_u32(&sXY[bf][p][o]),
                     &g_Exy[((b*NPTS + js)*NXH + ixh)*32 + o], sz);
            } else if (idx < 1024) {
                int p = (idx - 512) >> 4, o = ((idx - 512) & 15) * 2;
                int j = j0 + p;
                int js = (j < jend) ? j : jstart;
                int sz = (j < jend) ? 16 : 0;
                cp16(smem_u32(&sEz[bf][p][o]),
                     &g_Ez2[(b*NPTS + js)*32 + o], sz);
            } else {
                int p = idx - 1024;
                int j = j0 + p;
                int js = (j < jend) ? j : jstart;
                int sz = (j < jend) ? 16 : 0;
                cp16(smem_u32(&sQ[bf][p]), &charge[(b*NPTS + js)*NCH], sz);
            }
        }
    };

    u64 acc[2][NCH][4];
#pragma unroll
    for (int t = 0; t < 2; t++)
#pragma unroll
        for (int c = 0; c < NCH; c++)
#pragma unroll
            for (int zl = 0; zl < 4; zl++) acc[t][c][zl] = 0ull;

    stage(0, 0);
    cp_commit();

    for (int nck = 0; nck < NCHUNK; nck++) {
        const int bf = nck & 1;
        if (nck + 1 < NCHUNK) {
            stage(nck + 1, (nck + 1) & 1);
            cp_commit();
            cp_wait<1>();
        } else {
            cp_wait<0>();
        }
        __syncthreads();

#pragma unroll 2
        for (int p = 0; p < PCHUNK; p++) {
            float4 xy   = *reinterpret_cast<const float4*>(&sXY[bf][p][iy0]);
            float4 q    = sQ[bf][p];
            float4 ez01 = *reinterpret_cast<const float4*>(&sEz[bf][p][z0]);
            float4 ez23 = *reinterpret_cast<const float4*>(&sEz[bf][p][z0+2]);
            u64 exqA = pk(xy.x, xy.x), eyqA = pk(-xy.y, xy.y);
            u64 exqB = pk(xy.z, xy.z), eyqB = pk(-xy.w, xy.w);
            u64 q0 = pk(q.x, q.x), q1 = pk(q.y, q.y);
            u64 q2 = pk(q.z, q.z), q3 = pk(q.w, q.w);
            u64 ezv[4]  = { pk(ez01.x, ez01.y), pk(ez01.z, ez01.w),
                            pk(ez23.x, ez23.y), pk(ez23.z, ez23.w) };
            u64 ezvS[4] = { pk(ez01.y, ez01.x), pk(ez01.w, ez01.z),
                            pk(ez23.y, ez23.x), pk(ez23.w, ez23.z) };
#pragma unroll
            for (int zl = 0; zl < 4; zl++) {
                u64 xyzA = ffma2(eyqA, ezvS[zl], fmul2(exqA, ezv[zl]));
                u64 xyzB = ffma2(eyqB, ezvS[zl], fmul2(exqB, ezv[zl]));
                acc[0][0][zl] = ffma2(q0, xyzA, acc[0][0][zl]);
                acc[0][1][zl] = ffma2(q1, xyzA, acc[0][1][zl]);
                acc[0][2][zl] = ffma2(q2, xyzA, acc[0][2][zl]);
                acc[0][3][zl] = ffma2(q3, xyzA, acc[0][3][zl]);
                acc[1][0][zl] = ffma2(q0, xyzB, acc[1][0][zl]);
                acc[1][1][zl] = ffma2(q1, xyzB, acc[1][1][zl]);
                acc[1][2][zl] = ffma2(q2, xyzB, acc[1][2][zl]);
                acc[1][3][zl] = ffma2(q3, xyzB, acc[1][3][zl]);
            }
        }
        __syncthreads();
    }

#pragma unroll
    for (int t = 0; t < 2; t++) {
        int iy = iy0 + t;
        if (iy < NM) {
#pragma unroll
            for (int zl = 0; zl < 4; zl++) {
                int z = z0 + zl;
                if (z < NM) {
#pragma unroll
                    for (int c = 0; c < NCH; c++) {
                        g_Fp[(((split*NB + b)*NCH + c)*NXH + ixh)*NPLANE + iy*NM + z] =
                            upk(acc[t][c][zl]);
                    }
                }
            }
        }
    }
}

// ---------------------------------------------------------------------------
// 4b) Reduce partials + fold mult AND Hermitian weight into padded layout
// ---------------------------------------------------------------------------
__global__ void reduce_kernel() {
    int idx = blockIdx.x * blockDim.x + threadIdx.x;
    if (idx >= FPAD) return;
    int z   = idx & 31;
    int iy  = (idx >> 5) & 31;
    int c   = (idx >> 10) & 3;
    int ixh = (idx >> 12) & 15;
    int b   = idx >> 16;
    float2 s = make_float2(0.0f, 0.0f);
    if (z < NM && iy < NM) {
        const int TOT = NB*NCH*NXH*NPLANE;
        int src = (((b)*NCH + c)*NXH + ixh)*NPLANE + iy*NM + z;
#pragma unroll
        for (int sp = 0; sp < NSPLIT; sp++) {
            float2 v = g_Fp[sp*TOT + src];
            s.x += v.x; s.y += v.y;
        }
        float m = g_mult[(15 + ixh)*NPLANE + iy*NM + z];
        if (ixh > 0) m *= 2.0f;              // Hermitian half-space weight
        s.x *= m; s.y *= m;
    }
    g_F2[idx] = s;
}

// ---------------------------------------------------------------------------
// 5) Gather (r6 form + register double-buffered F planes). One CTA per
//    (batch, 8 particles). F read directly from padded L2-resident tensor;
//    next plane's Fr tile is loaded into a second register set while the
//    current plane computes, hiding the L2 latency chain.
// ---------------------------------------------------------------------------
__global__ void __launch_bounds__(256, 2) gather_kernel(const float* __restrict__ charge,
                                                        float* __restrict__ out) {
    const int b   = blockIdx.y;
    const int j0  = blockIdx.x * 8;
    const int tid = threadIdx.x;
    const int iy  = tid >> 3;
    const int zh  = (tid & 7) * 2;       // z0 = zh*2
    const bool act = (iy < NM);
    const int warp = tid >> 5;
    const int lane = tid & 31;

    __shared__ float2     pEx[8][NXH];   // plain Ex (weight folded in reduce)
    __shared__ float2     pEy[8][32];
    __shared__ ulonglong2 pEz[8][16];    // z pairs, slot z=31 zero
    __shared__ float4     pCh[8];
    __shared__ float      red[8][32];
    __shared__ float      sfin[32];

    u64* pEzU = reinterpret_cast<u64*>(pEz);

    // particle data from g_E3
    for (int idx = tid; idx < 8*32; idx += 256) {
        int p = idx >> 5, i = idx & 31;
        int base = (b*NPTS + j0 + p) * 3;
        pEy[p][i] = g_E3[(base + 1)*32 + i];
        float2 vz = g_E3[(base + 2)*32 + i];
        pEzU[p*32 + i] = pk(vz.x, vz.y);
    }
    if (tid < 8*NXH) {
        int p = tid >> 4, i = tid & 15;
        pEx[p][i] = g_E3[((b*NPTS + j0 + p)*3 + 0)*32 + 15 + i];
    }
    if (tid < 8) {
        pCh[tid] = *reinterpret_cast<const float4*>(&charge[(b*NPTS + j0 + tid)*NCH]);
    }
    __syncthreads();

    u64 acc[8][NCH];
#pragma unroll
    for (int p = 0; p < 8; p++)
#pragma unroll
        for (int c = 0; c < NCH; c++) acc[p][c] = 0ull;

    const ulonglong2* Fbase = reinterpret_cast<const ulonglong2*>(g_F2);

    u64 Fr[NCH][4];
    if (act) {
#pragma unroll
        for (int c = 0; c < NCH; c++) {
            const ulonglong2* fp = Fbase + (((b*NXH + 0)*NCH + c)*32 + iy)*16 + zh;
            ulonglong2 f0 = fp[0], f1 = fp[1];
            Fr[c][0] = f0.x; Fr[c][1] = f0.y; Fr[c][2] = f1.x; Fr[c][3] = f1.y;
        }
    }

    for (int ixh = 0; ixh < NXH; ixh++) {
        if (act) {
            // register prefetch of next plane (independent LDG.128s; consumed
            // only after this plane's 192 FMA2, so latency is fully covered)
            u64 Fn[NCH][4];
            if (ixh + 1 < NXH) {
#pragma unroll
                for (int c = 0; c < NCH; c++) {
                    const ulonglong2* fp =
                        Fbase + (((b*NXH + (ixh+1))*NCH + c)*32 + iy)*16 + zh;
                    ulonglong2 f0 = fp[0], f1 = fp[1];
                    Fn[c][0] = f0.x; Fn[c][1] = f0.y; Fn[c][2] = f1.x; Fn[c][3] = f1.y;
                }
            }
#pragma unroll
            for (int p = 0; p < 8; p++) {
                float2 exy = cmul(pEx[p][ixh], pEy[p][iy]);
                u64 exq = pk(exy.x, exy.x);
                u64 eyq = pk(-exy.y, exy.y);
                ulonglong2 ez01 = pEz[p][zh];
                ulonglong2 ez23 = pEz[p][zh + 1];
                u64 ezv[4] = {ez01.x, ez01.y, ez23.x, ez23.y};
#pragma unroll
                for (int zl = 0; zl < 4; zl++) {
                    u64 ez = ezv[zl];
                    u64 e2 = ffma2(eyq, swap64(ez), fmul2(exq, ez));   // exy*ez
                    acc[p][0] = ffma2(e2, Fr[0][zl], acc[p][0]);
                    acc[p][1] = ffma2(e2, Fr[1][zl], acc[p][1]);
                    acc[p][2] = ffma2(e2, Fr[2][zl], acc[p][2]);
                    acc[p][3] = ffma2(e2, Fr[3][zl], acc[p][3]);
                }
            }
            if (ixh + 1 < NXH) {
#pragma unroll
                for (int c = 0; c < NCH; c++)
#pragma unroll
                    for (int zl = 0; zl < 4; zl++) Fr[c][zl] = Fn[c][zl];
            }
        }
    }
    __syncthreads();

    // horizontal add (Re part) then block reduction
#pragma unroll
    for (int p = 0; p < 8; p++) {
#pragma unroll
        for (int c = 0; c < NCH; c++) {
            float2 f = upk(acc[p][c]);
            float v = f.x + f.y;
#pragma unroll
            for (int off = 16; off > 0; off >>= 1)
                v += __shfl_xor_sync(0xffffffffu, v, off);
            if (lane == 0) red[warp][p*NCH + c] = v;
        }
    }
    __syncthreads();
    if (tid < 32) {
        float s = 0.0f;
#pragma unroll
        for (int w = 0; w < 8; w++) s += red[w][tid];
        sfin[tid] = s;
    }
    __syncthreads();
    if (tid < 8) {
        float diag = g_diag;
        float4 c4 = pCh[tid];
        float e = c4.x * (sfin[tid*NCH + 0]*INV2V - diag)
                + c4.y * (sfin[tid*NCH + 1]*INV2V - diag)
                + c4.z * (sfin[tid*NCH + 2]*INV2V - diag)
                + c4.w * (sfin[tid*NCH + 3]*INV2V - diag);
        out[b*NPTS + j0 + tid] = e;
    }
}

// ---------------------------------------------------------------------------
// Launch
// ---------------------------------------------------------------------------
extern "C" void kernel_launch(void* const* d_in, const int* in_sizes, int n_in,
                              void* d_out, int out_size) {
    const float* pos    = (const float*)d_in[0];
    const float* charge = (const float*)d_in[1];
    const float* shift  = (const float*)d_in[2];
    const float* amp    = (const float*)d_in[3];
    float* out = (float*)d_out;

    mult_kernel<<<(NK + 255)/256, 256>>>(shift, amp);
    diag_kernel<<<1, 1024>>>();
    etab_kernel<<<(NB*NPTS*32 + 255)/256, 256>>>(pos);
    scatter_kernel<<<dim3(NXH, NB, NSPLIT), 128>>>(charge);
    reduce_kernel<<<(FPAD + 255)/256, 256>>>();
    gather_kernel<<<dim3(NPTS/8, NB), 256>>>(charge, out);
}

// round 13
// speedup vs baseline: 1.4554x; 1.4554x over previous
#include <cuda_runtime.h>
#include <cstdint>

// Problem constants
#define NM      31
#define NPLANE  (NM*NM)        // 961
#define NK      (NM*NM*NM)     // 29791
#define NB      8
#define NPTS    3000
#define NCH     4
#define NBW     12
#define NXH     16             // half-space planes nx = 0..15
#define NSPLIT  4
#define JCHUNK  (NPTS/NSPLIT)  // 750
#define PCHUNK  32             // particles per pipeline stage
#define NCHUNK  ((JCHUNK + PCHUNK - 1)/PCHUNK)   // 24
#define TWO_PI_L 0.628318530717958647692f
#define HALF_L   5.0f
#define INV2V    (1.0f/2000.0f)

typedef unsigned long long u64;

// Padded F tensor: [b][ixh][c][iy:32][z:32], zero-padded at iy=31 / z=31
#define FPAD    (NB*NXH*NCH*32*32)     // 524288 float2 = 4.2 MB

// Scratch (static device globals; allocation-free per harness rules)
__device__ __align__(256) float2 g_Exy[NB*NPTS*NXH*32];  // [pidx][ixh][i], 98.3 MB
__device__ __align__(256) float2 g_Ez2[NB*NPTS*32];      // [pidx][i], 6.1 MB
__device__ __align__(256) float2 g_E3[NB*NPTS*3*32];     // [pidx][dim][i], 18.4 MB
__device__ float2 g_Fp[NSPLIT*NB*NCH*NXH*NPLANE];        // partial structure factors
__device__ float2 g_F2[FPAD];                            // mult(+w)-folded, padded
__device__ float  g_mult[NK];
__device__ float  g_diag;

__device__ __forceinline__ float2 cmul(float2 a, float2 b) {
    return make_float2(a.x*b.x - a.y*b.y, a.x*b.y + a.y*b.x);
}
__device__ __forceinline__ u64 pk(float x, float y) {
    u64 r; asm("mov.b64 %0,{%1,%2};" : "=l"(r) : "f"(x), "f"(y)); return r;
}
__device__ __forceinline__ float2 upk(u64 v) {
    float2 f; asm("mov.b64 {%0,%1},%2;" : "=f"(f.x), "=f"(f.y) : "l"(v)); return f;
}
__device__ __forceinline__ u64 swap64(u64 v) {
    float2 f = upk(v); return pk(f.y, f.x);
}
__device__ __forceinline__ u64 ffma2(u64 a, u64 b, u64 c) {
    u64 d; asm("fma.rn.f32x2 %0,%1,%2,%3;" : "=l"(d) : "l"(a), "l"(b), "l"(c)); return d;
}
__device__ __forceinline__ u64 fmul2(u64 a, u64 b) {
    u64 d; asm("mul.rn.f32x2 %0,%1,%2;" : "=l"(d) : "l"(a), "l"(b)); return d;
}
__device__ __forceinline__ uint32_t smem_u32(const void* p) {
    return static_cast<uint32_t>(__cvta_generic_to_shared(p));
}
__device__ __forceinline__ void cp16(uint32_t dst, const void* src, int srcsz) {
    asm volatile("cp.async.cg.shared.global [%0],[%1],16,%2;"
                 :: "r"(dst), "l"(src), "r"(srcsz));
}
__device__ __forceinline__ void cp_commit() {
    asm volatile("cp.async.commit_group;");
}
template<int N> __device__ __forceinline__ void cp_wait() {
    asm volatile("cp.async.wait_group %0;" :: "n"(N));
}

// ---------------------------------------------------------------------------
// 1) mult(k)
// ---------------------------------------------------------------------------
__global__ void mult_kernel(const float* __restrict__ shift,
                            const float* __restrict__ amp) {
    int i = blockIdx.x * blockDim.x + threadIdx.x;
    if (i >= NK) return;
    int ix = i / NPLANE;
    int r  = i - ix * NPLANE;
    int iy = r / NM;
    int iz = r - iy * NM;
    float kx = TWO_PI_L * (float)(ix - 15);
    float ky = TWO_PI_L * (float)(iy - 15);
    float kz = TWO_PI_L * (float)(iz - 15);
    float k2 = kx*kx + ky*ky + kz*kz;
    float m = 0.0f;
#pragma unroll
    for (int b = 0; b < NBW; b++) {
        m += amp[b] * __expf(-k2 * __expf(2.0f * shift[b]));
    }
    if (k2 == 0.0f) m = 0.0f;
    g_mult[i] = m;
}

// ---------------------------------------------------------------------------
// 2) diag_sum
// ---------------------------------------------------------------------------
__global__ void diag_kernel() {
    __shared__ float sh[1024];
    int tid = threadIdx.x;
    float s = 0.0f;
    for (int i = tid; i < NK; i += 1024) s += g_mult[i];
    sh[tid] = s;
    __syncthreads();
    for (int o = 512; o > 0; o >>= 1) {
        if (tid < o) sh[tid] += sh[tid + o];
        __syncthreads();
    }
    if (tid == 0) g_diag = sh[0] * INV2V;
}

// ---------------------------------------------------------------------------
// 3) E tables: one warp per particle, coalesced 256B row stores.
//    Emits: g_Exy (scatter), g_Ez2 (scatter), g_E3 (gather ex/ey/ez).
// ---------------------------------------------------------------------------
__global__ void etab_kernel(const float* __restrict__ pos) {
    int gw   = (blockIdx.x * blockDim.x + threadIdx.x) >> 5;  // particle
    int lane = threadIdx.x & 31;
    if (gw >= NB * NPTS) return;

    float tx = TWO_PI_L * (pos[gw*3 + 0] - HALF_L);
    float ty = TWO_PI_L * (pos[gw*3 + 1] - HALF_L);
    float tz = TWO_PI_L * (pos[gw*3 + 2] - HALF_L);

    float n = (float)(lane - 15);
    float sy, cy, sz, cz;
    sincosf(n * ty, &sy, &cy);
    sincosf(n * tz, &sz, &cz);
    bool valid = (lane < NM);
    float2 ey = valid ? make_float2(cy, -sy) : make_float2(0.f, 0.f);
    float2 ez = valid ? make_float2(cz, -sz) : make_float2(0.f, 0.f);

    g_Ez2[gw*32 + lane] = ez;
    g_E3[(gw*3 + 1)*32 + lane] = ey;
    g_E3[(gw*3 + 2)*32 + lane] = ez;

    float sx, cx;
    sincosf(tx, &sx, &cx);
    float2 e1x = make_float2(cx, -sx);
    float2 ex  = make_float2(1.f, 0.f);
    float2* row = &g_Exy[gw * (NXH*32)];
#pragma unroll
    for (int it = 0; it < NXH; it++) {
        if (lane == 0) g_E3[(gw*3 + 0)*32 + 15 + it] = ex;  // Ex[nx=it]
        row[it*32 + lane] = cmul(ex, ey);
        ex = cmul(ex, e1x);
    }
}

// ---------------------------------------------------------------------------
// 4) Scatter (r7 form, measured 278-280 us across 3 runs). 128-thread CTA
//    per (ixh, b, split); thread tile (2 iy) x (4 z) x (4 ch).
//    Double-buffered cp.async staging.
// ---------------------------------------------------------------------------
__global__ void __launch_bounds__(128, 4) scatter_kernel(const float* __restrict__ charge) {
    const int ixh   = blockIdx.x;        // 0..15
    const int b     = blockIdx.y;
    const int split = blockIdx.z;
    const int tid   = threadIdx.x;
    const int iy0   = (tid >> 3) * 2;    // 0,2,..,30
    const int z0    = (tid & 7) * 4;     // 0,4,..,28
    const int jstart = split * JCHUNK;
    const int jend   = jstart + JCHUNK;

    __shared__ __align__(128) float2 sXY[2][PCHUNK][32];   // raw exy   2x8 KB
    __shared__ __align__(128) float2 sEz[2][PCHUNK][32];   //           2x8 KB
    __shared__ __align__(128) float4 sQ [2][PCHUNK];       //           2x0.5 KB

    auto stage = [&](int cn, int bf) {
        int j0 = jstart + cn * PCHUNK;
        for (int idx = tid; idx < 1056; idx += 128) {
            if (idx < 512) {
                int p = idx >> 4, o = (idx & 15) * 2;
                int j = j0 + p;
                int js = (j < jend) ? j : jstart;
                int sz = (j < jend) ? 16 : 0;
                cp16(smem_u32(&sXY[bf][p][o]),
                     &g_Exy[((b*NPTS + js)*NXH + ixh)*32 + o], sz);
            } else if (idx < 1024) {
                int p = (idx - 512) >> 4, o = ((idx - 512) & 15) * 2;
                int j = j0 + p;
                int js = (j < jend) ? j : jstart;
                int sz = (j < jend) ? 16 : 0;
                cp16(smem_u32(&sEz[bf][p][o]),
                     &g_Ez2[(b*NPTS + js)*32 + o], sz);
            } else {
                int p = idx - 1024;
                int j = j0 + p;
                int js = (j < jend) ? j : jstart;
                int sz = (j < jend) ? 16 : 0;
                cp16(smem_u32(&sQ[bf][p]), &charge[(b*NPTS + js)*NCH], sz);
            }
        }
    };

    u64 acc[2][NCH][4];
#pragma unroll
    for (int t = 0; t < 2; t++)
#pragma unroll
        for (int c = 0; c < NCH; c++)
#pragma unroll
            for (int zl = 0; zl < 4; zl++) acc[t][c][zl] = 0ull;

    stage(0, 0);
    cp_commit();

    for (int nck = 0; nck < NCHUNK; nck++) {
        const int bf = nck & 1;
        if (nck + 1 < NCHUNK) {
            stage(nck + 1, (nck + 1) & 1);
            cp_commit();
            cp_wait<1>();
        } else {
            cp_wait<0>();
        }
        __syncthreads();

#pragma unroll 2
        for (int p = 0; p < PCHUNK; p++) {
            float4 xy   = *reinterpret_cast<const float4*>(&sXY[bf][p][iy0]);
            float4 q    = sQ[bf][p];
            float4 ez01 = *reinterpret_cast<const float4*>(&sEz[bf][p][z0]);
            float4 ez23 = *reinterpret_cast<const float4*>(&sEz[bf][p][z0+2]);
            u64 exqA = pk(xy.x, xy.x), eyqA = pk(-xy.y, xy.y);
            u64 exqB = pk(xy.z, xy.z), eyqB = pk(-xy.w, xy.w);
            u64 q0 = pk(q.x, q.x), q1 = pk(q.y, q.y);
            u64 q2 = pk(q.z, q.z), q3 = pk(q.w, q.w);
            u64 ezv[4]  = { pk(ez01.x, ez01.y), pk(ez01.z, ez01.w),
                            pk(ez23.x, ez23.y), pk(ez23.z, ez23.w) };
            u64 ezvS[4] = { pk(ez01.y, ez01.x), pk(ez01.w, ez01.z),
                            pk(ez23.y, ez23.x), pk(ez23.w, ez23.z) };
#pragma unroll
            for (int zl = 0; zl < 4; zl++) {
                u64 xyzA = ffma2(eyqA, ezvS[zl], fmul2(exqA, ezv[zl]));
                u64 xyzB = ffma2(eyqB, ezvS[zl], fmul2(exqB, ezv[zl]));
                acc[0][0][zl] = ffma2(q0, xyzA, acc[0][0][zl]);
                acc[0][1][zl] = ffma2(q1, xyzA, acc[0][1][zl]);
                acc[0][2][zl] = ffma2(q2, xyzA, acc[0][2][zl]);
                acc[0][3][zl] = ffma2(q3, xyzA, acc[0][3][zl]);
                acc[1][0][zl] = ffma2(q0, xyzB, acc[1][0][zl]);
                acc[1][1][zl] = ffma2(q1, xyzB, acc[1][1][zl]);
                acc[1][2][zl] = ffma2(q2, xyzB, acc[1][2][zl]);
                acc[1][3][zl] = ffma2(q3, xyzB, acc[1][3][zl]);
            }
        }
        __syncthreads();
    }

#pragma unroll
    for (int t = 0; t < 2; t++) {
        int iy = iy0 + t;
        if (iy < NM) {
#pragma unroll
            for (int zl = 0; zl < 4; zl++) {
                int z = z0 + zl;
                if (z < NM) {
#pragma unroll
                    for (int c = 0; c < NCH; c++) {
                        g_Fp[(((split*NB + b)*NCH + c)*NXH + ixh)*NPLANE + iy*NM + z] =
                            upk(acc[t][c][zl]);
                    }
                }
            }
        }
    }
}

// ---------------------------------------------------------------------------
// 4b) Reduce partials + fold mult AND Hermitian weight into padded layout
// ---------------------------------------------------------------------------
__global__ void reduce_kernel() {
    int idx = blockIdx.x * blockDim.x + threadIdx.x;
    if (idx >= FPAD) return;
    int z   = idx & 31;
    int iy  = (idx >> 5) & 31;
    int c   = (idx >> 10) & 3;
    int ixh = (idx >> 12) & 15;
    int b   = idx >> 16;
    float2 s = make_float2(0.0f, 0.0f);
    if (z < NM && iy < NM) {
        const int TOT = NB*NCH*NXH*NPLANE;
        int src = (((b)*NCH + c)*NXH + ixh)*NPLANE + iy*NM + z;
#pragma unroll
        for (int sp = 0; sp < NSPLIT; sp++) {
            float2 v = g_Fp[sp*TOT + src];
            s.x += v.x; s.y += v.y;
        }
        float m = g_mult[(15 + ixh)*NPLANE + iy*NM + z];
        if (ixh > 0) m *= 2.0f;              // Hermitian half-space weight
        s.x *= m; s.y *= m;
    }
    g_F2[idx] = s;
}

// ---------------------------------------------------------------------------
// 5) Gather (r6 form, measured ~290 us). One CTA per (batch, 8 particles).
//    Fr loaded in-loop via coalesced LDG.128 from the padded L2-resident
//    tensor; zero-register-cost L1 prefetch of the next plane. No register
//    double-buffer (r12's spill lesson: acc64+Fr32+Fn32 > budget).
// ---------------------------------------------------------------------------
__global__ void __launch_bounds__(256, 2) gather_kernel(const float* __restrict__ charge,
                                                        float* __restrict__ out) {
    const int b   = blockIdx.y;
    const int j0  = blockIdx.x * 8;
    const int tid = threadIdx.x;
    const int iy  = tid >> 3;
    const int zh  = (tid & 7) * 2;       // z0 = zh*2
    const bool act = (iy < NM);
    const int warp = tid >> 5;
    const int lane = tid & 31;

    __shared__ float2     pEx[8][NXH];
    __shared__ float2     pEy[8][32];
    __shared__ ulonglong2 pEz[8][16];    // z pairs, slot z=31 zero
    __shared__ float4     pCh[8];
    __shared__ float      red[8][32];
    __shared__ float      sfin[32];

    u64* pEzU = reinterpret_cast<u64*>(pEz);

    // particle data from g_E3
    for (int idx = tid; idx < 8*32; idx += 256) {
        int p = idx >> 5, i = idx & 31;
        int base = (b*NPTS + j0 + p) * 3;
        pEy[p][i] = g_E3[(base + 1)*32 + i];
        float2 vz = g_E3[(base + 2)*32 + i];
        pEzU[p*32 + i] = pk(vz.x, vz.y);
    }
    if (tid < 8*NXH) {
        int p = tid >> 4, i = tid & 15;
        pEx[p][i] = g_E3[((b*NPTS + j0 + p)*3 + 0)*32 + 15 + i];
    }
    if (tid < 8) {
        pCh[tid] = *reinterpret_cast<const float4*>(&charge[(b*NPTS + j0 + tid)*NCH]);
    }
    __syncthreads();

    u64 acc[8][NCH];
#pragma unroll
    for (int p = 0; p < 8; p++)
#pragma unroll
        for (int c = 0; c < NCH; c++) acc[p][c] = 0ull;

    const ulonglong2* Fbase = reinterpret_cast<const ulonglong2*>(g_F2);

    for (int ixh = 0; ixh < NXH; ixh++) {
        if (act) {
            u64 Fr[NCH][4];
#pragma unroll
            for (int c = 0; c < NCH; c++) {
                const ulonglong2* fp =
                    Fbase + (((b*NXH + ixh)*NCH + c)*32 + iy)*16 + zh;
                ulonglong2 f0 = fp[0];
                ulonglong2 f1 = fp[1];
                Fr[c][0] = f0.x; Fr[c][1] = f0.y;
                Fr[c][2] = f1.x; Fr[c][3] = f1.y;
            }
            // next plane's lines into L1 (zero register cost)
            if (ixh + 1 < NXH) {
#pragma unroll
                for (int c = 0; c < NCH; c++) {
                    const ulonglong2* np =
                        Fbase + (((b*NXH + (ixh+1))*NCH + c)*32 + iy)*16 + zh;
                    asm volatile("prefetch.global.L1 [%0];" :: "l"(np));
                }
            }
#pragma unroll
            for (int p = 0; p < 8; p++) {
                float2 exy = cmul(pEx[p][ixh], pEy[p][iy]);
                u64 exq = pk(exy.x, exy.x);
                u64 eyq = pk(-exy.y, exy.y);
                ulonglong2 ez01 = pEz[p][zh];
                ulonglong2 ez23 = pEz[p][zh + 1];
                u64 ezv[4] = {ez01.x, ez01.y, ez23.x, ez23.y};
#pragma unroll
                for (int zl = 0; zl < 4; zl++) {
                    u64 ez = ezv[zl];
                    u64 e2 = ffma2(eyq, swap64(ez), fmul2(exq, ez));   // exy*ez
                    acc[p][0] = ffma2(e2, Fr[0][zl], acc[p][0]);
                    acc[p][1] = ffma2(e2, Fr[1][zl], acc[p][1]);
                    acc[p][2] = ffma2(e2, Fr[2][zl], acc[p][2]);
                    acc[p][3] = ffma2(e2, Fr[3][zl], acc[p][3]);
                }
            }
        }
    }
    __syncthreads();

    // horizontal add (Re part) then block reduction
#pragma unroll
    for (int p = 0; p < 8; p++) {
#pragma unroll
        for (int c = 0; c < NCH; c++) {
            float2 f = upk(acc[p][c]);
            float v = f.x + f.y;
#pragma unroll
            for (int off = 16; off > 0; off >>= 1)
                v += __shfl_xor_sync(0xffffffffu, v, off);
            if (lane == 0) red[warp][p*NCH + c] = v;
        }
    }
    __syncthreads();
    if (tid < 32) {
        float s = 0.0f;
#pragma unroll
        for (int w = 0; w < 8; w++) s += red[w][tid];
        sfin[tid] = s;
    }
    __syncthreads();
    if (tid < 8) {
        float diag = g_diag;
        float4 c4 = pCh[tid];
        float e = c4.x * (sfin[tid*NCH + 0]*INV2V - diag)
                + c4.y * (sfin[tid*NCH + 1]*INV2V - diag)
                + c4.z * (sfin[tid*NCH + 2]*INV2V - diag)
                + c4.w * (sfin[tid*NCH + 3]*INV2V - diag);
        out[b*NPTS + j0 + tid] = e;
    }
}

// ---------------------------------------------------------------------------
// Launch
// ---------------------------------------------------------------------------
extern "C" void kernel_launch(void* const* d_in, const int* in_sizes, int n_in,
                              void* d_out, int out_size) {
    const float* pos    = (const float*)d_in[0];
    const float* charge = (const float*)d_in[1];
    const float* shift  = (const float*)d_in[2];
    const float* amp    = (const float*)d_in[3];
    float* out = (float*)d_out;

    mult_kernel<<<(NK + 255)/256, 256>>>(shift, amp);
    diag_kernel<<<1, 1024>>>();
    etab_kernel<<<(NB*NPTS*32 + 255)/256, 256>>>(pos);
    scatter_kernel<<<dim3(NXH, NB, NSPLIT), 128>>>(charge);
    reduce_kernel<<<(FPAD + 255)/256, 256>>>();
    gather_kernel<<<dim3(NPTS/8, NB), 256>>>(charge, out);
}

// round 14
// speedup vs baseline: 1.5105x; 1.0378x over previous
#include <cuda_runtime.h>
#include <cstdint>

// Problem constants
#define NM      31
#define NPLANE  (NM*NM)        // 961
#define NK      (NM*NM*NM)     // 29791
#define NB      8
#define NPTS    3000
#define NCH     4
#define NBW     12
#define NXH     16             // half-space planes nx = 0..15
#define NSPLIT  4
#define JCHUNK  (NPTS/NSPLIT)  // 750
#define PCHUNK  32             // particles per pipeline stage
#define NCHUNK  ((JCHUNK + PCHUNK - 1)/PCHUNK)   // 24
#define TWO_PI_L 0.628318530717958647692f
#define HALF_L   5.0f
#define INV2V    (1.0f/2000.0f)

typedef unsigned long long u64;

// Padded F tensor: [b][ixh][c][iy:32][z:32], zero-padded at iy=31 / z=31
#define FPAD    (NB*NXH*NCH*32*32)     // 524288 float2 = 4.2 MB

// Scratch (static device globals; allocation-free per harness rules)
__device__ __align__(256) float2 g_Exy[NB*NPTS*NXH*32];  // [pidx][ixh][i], 98.3 MB
__device__ __align__(256) float2 g_Ez2[NB*NPTS*32];      // [pidx][i], 6.1 MB
__device__ __align__(256) float2 g_E3[NB*NPTS*3*32];     // [pidx][dim][i], 18.4 MB
__device__ float2 g_Fp[NSPLIT*NB*NCH*NXH*NPLANE];        // partial structure factors
__device__ float2 g_F2[FPAD];                            // mult(+w)-folded, padded
__device__ float  g_mult[NK];
__device__ float  g_diag;

__device__ __forceinline__ float2 cmul(float2 a, float2 b) {
    return make_float2(a.x*b.x - a.y*b.y, a.x*b.y + a.y*b.x);
}
__device__ __forceinline__ u64 pk(float x, float y) {
    u64 r; asm("mov.b64 %0,{%1,%2};" : "=l"(r) : "f"(x), "f"(y)); return r;
}
__device__ __forceinline__ float2 upk(u64 v) {
    float2 f; asm("mov.b64 {%0,%1},%2;" : "=f"(f.x), "=f"(f.y) : "l"(v)); return f;
}
__device__ __forceinline__ u64 swap64(u64 v) {
    float2 f = upk(v); return pk(f.y, f.x);
}
__device__ __forceinline__ u64 ffma2(u64 a, u64 b, u64 c) {
    u64 d; asm("fma.rn.f32x2 %0,%1,%2,%3;" : "=l"(d) : "l"(a), "l"(b), "l"(c)); return d;
}
__device__ __forceinline__ u64 fmul2(u64 a, u64 b) {
    u64 d; asm("mul.rn.f32x2 %0,%1,%2;" : "=l"(d) : "l"(a), "l"(b)); return d;
}
__device__ __forceinline__ uint32_t smem_u32(const void* p) {
    return static_cast<uint32_t>(__cvta_generic_to_shared(p));
}
__device__ __forceinline__ void cp16(uint32_t dst, const void* src, int srcsz) {
    asm volatile("cp.async.cg.shared.global [%0],[%1],16,%2;"
                 :: "r"(dst), "l"(src), "r"(srcsz));
}
__device__ __forceinline__ void cp_commit() {
    asm volatile("cp.async.commit_group;");
}
template<int N> __device__ __forceinline__ void cp_wait() {
    asm volatile("cp.async.wait_group %0;" :: "n"(N));
}

// ---------------------------------------------------------------------------
// 1) mult(k)
// ---------------------------------------------------------------------------
__global__ void mult_kernel(const float* __restrict__ shift,
                            const float* __restrict__ amp) {
    int i = blockIdx.x * blockDim.x + threadIdx.x;
    if (i >= NK) return;
    int ix = i / NPLANE;
    int r  = i - ix * NPLANE;
    int iy = r / NM;
    int iz = r - iy * NM;
    float kx = TWO_PI_L * (float)(ix - 15);
    float ky = TWO_PI_L * (float)(iy - 15);
    float kz = TWO_PI_L * (float)(iz - 15);
    float k2 = kx*kx + ky*ky + kz*kz;
    float m = 0.0f;
#pragma unroll
    for (int b = 0; b < NBW; b++) {
        m += amp[b] * __expf(-k2 * __expf(2.0f * shift[b]));
    }
    if (k2 == 0.0f) m = 0.0f;
    g_mult[i] = m;
}

// ---------------------------------------------------------------------------
// 2) diag_sum
// ---------------------------------------------------------------------------
__global__ void diag_kernel() {
    __shared__ float sh[1024];
    int tid = threadIdx.x;
    float s = 0.0f;
    for (int i = tid; i < NK; i += 1024) s += g_mult[i];
    sh[tid] = s;
    __syncthreads();
    for (int o = 512; o > 0; o >>= 1) {
        if (tid < o) sh[tid] += sh[tid + o];
        __syncthreads();
    }
    if (tid == 0) g_diag = sh[0] * INV2V;
}

// ---------------------------------------------------------------------------
// 3) E tables: one warp per particle, coalesced 256B row stores.
//    Emits: g_Exy (scatter), g_Ez2 (scatter), g_E3 (gather ex/ey/ez).
// ---------------------------------------------------------------------------
__global__ void etab_kernel(const float* __restrict__ pos) {
    int gw   = (blockIdx.x * blockDim.x + threadIdx.x) >> 5;  // particle
    int lane = threadIdx.x & 31;
    if (gw >= NB * NPTS) return;

    float tx = TWO_PI_L * (pos[gw*3 + 0] - HALF_L);
    float ty = TWO_PI_L * (pos[gw*3 + 1] - HALF_L);
    float tz = TWO_PI_L * (pos[gw*3 + 2] - HALF_L);

    float n = (float)(lane - 15);
    float sy, cy, sz, cz;
    sincosf(n * ty, &sy, &cy);
    sincosf(n * tz, &sz, &cz);
    bool valid = (lane < NM);
    float2 ey = valid ? make_float2(cy, -sy) : make_float2(0.f, 0.f);
    float2 ez = valid ? make_float2(cz, -sz) : make_float2(0.f, 0.f);

    g_Ez2[gw*32 + lane] = ez;
    g_E3[(gw*3 + 1)*32 + lane] = ey;
    g_E3[(gw*3 + 2)*32 + lane] = ez;

    float sx, cx;
    sincosf(tx, &sx, &cx);
    float2 e1x = make_float2(cx, -sx);
    float2 ex  = make_float2(1.f, 0.f);
    float2* row = &g_Exy[gw * (NXH*32)];
#pragma unroll
    for (int it = 0; it < NXH; it++) {
        if (lane == 0) g_E3[(gw*3 + 0)*32 + 15 + it] = ex;  // Ex[nx=it]
        row[it*32 + lane] = cmul(ex, ey);
        ex = cmul(ex, e1x);
    }
}

// ---------------------------------------------------------------------------
// 4) Scatter (r7 form, measured 278-280 us across 4 runs — FROZEN).
//    128-thread CTA per (ixh, b, split); thread tile (2 iy) x (4 z) x (4 ch).
//    Double-buffered cp.async staging.
// ---------------------------------------------------------------------------
__global__ void __launch_bounds__(128, 4) scatter_kernel(const float* __restrict__ charge) {
    const int ixh   = blockIdx.x;        // 0..15
    const int b     = blockIdx.y;
    const int split = blockIdx.z;
    const int tid   = threadIdx.x;
    const int iy0   = (tid >> 3) * 2;    // 0,2,..,30
    const int z0    = (tid & 7) * 4;     // 0,4,..,28
    const int jstart = split * JCHUNK;
    const int jend   = jstart + JCHUNK;

    __shared__ __align__(128) float2 sXY[2][PCHUNK][32];   // raw exy   2x8 KB
    __shared__ __align__(128) float2 sEz[2][PCHUNK][32];   //           2x8 KB
    __shared__ __align__(128) float4 sQ [2][PCHUNK];       //           2x0.5 KB

    auto stage = [&](int cn, int bf) {
        int j0 = jstart + cn * PCHUNK;
        for (int idx = tid; idx < 1056; idx += 128) {
            if (idx < 512) {
                int p = idx >> 4, o = (idx & 15) * 2;
                int j = j0 + p;
                int js = (j < jend) ? j : jstart;
                int sz = (j < jend) ? 16 : 0;
                cp16(smem_u32(&sXY[bf][p][o]),
                     &g_Exy[((b*NPTS + js)*NXH + ixh)*32 + o], sz);
            } else if (idx < 1024) {
                int p = (idx - 512) >> 4, o = ((idx - 512) & 15) * 2;
                int j = j0 + p;
                int js = (j < jend) ? j : jstart;
                int sz = (j < jend) ? 16 : 0;
                cp16(smem_u32(&sEz[bf][p][o]),
                     &g_Ez2[(b*NPTS + js)*32 + o], sz);
            } else {
                int p = idx - 1024;
                int j = j0 + p;
                int js = (j < jend) ? j : jstart;
                int sz = (j < jend) ? 16 : 0;
                cp16(smem_u32(&sQ[bf][p]), &charge[(b*NPTS + js)*NCH], sz);
            }
        }
    };

    u64 acc[2][NCH][4];
#pragma unroll
    for (int t = 0; t < 2; t++)
#pragma unroll
        for (int c = 0; c < NCH; c++)
#pragma unroll
            for (int zl = 0; zl < 4; zl++) acc[t][c][zl] = 0ull;

    stage(0, 0);
    cp_commit();

    for (int nck = 0; nck < NCHUNK; nck++) {
        const int bf = nck & 1;
        if (nck + 1 < NCHUNK) {
            stage(nck + 1, (nck + 1) & 1);
            cp_commit();
            cp_wait<1>();
        } else {
            cp_wait<0>();
        }
        __syncthreads();

#pragma unroll 2
        for (int p = 0; p < PCHUNK; p++) {
            float4 xy   = *reinterpret_cast<const float4*>(&sXY[bf][p][iy0]);
            float4 q    = sQ[bf][p];
            float4 ez01 = *reinterpret_cast<const float4*>(&sEz[bf][p][z0]);
            float4 ez23 = *reinterpret_cast<const float4*>(&sEz[bf][p][z0+2]);
            u64 exqA = pk(xy.x, xy.x), eyqA = pk(-xy.y, xy.y);
            u64 exqB = pk(xy.z, xy.z), eyqB = pk(-xy.w, xy.w);
            u64 q0 = pk(q.x, q.x), q1 = pk(q.y, q.y);
            u64 q2 = pk(q.z, q.z), q3 = pk(q.w, q.w);
            u64 ezv[4]  = { pk(ez01.x, ez01.y), pk(ez01.z, ez01.w),
                            pk(ez23.x, ez23.y), pk(ez23.z, ez23.w) };
            u64 ezvS[4] = { pk(ez01.y, ez01.x), pk(ez01.w, ez01.z),
                            pk(ez23.y, ez23.x), pk(ez23.w, ez23.z) };
#pragma unroll
            for (int zl = 0; zl < 4; zl++) {
                u64 xyzA = ffma2(eyqA, ezvS[zl], fmul2(exqA, ezv[zl]));
                u64 xyzB = ffma2(eyqB, ezvS[zl], fmul2(exqB, ezv[zl]));
                acc[0][0][zl] = ffma2(q0, xyzA, acc[0][0][zl]);
                acc[0][1][zl] = ffma2(q1, xyzA, acc[0][1][zl]);
                acc[0][2][zl] = ffma2(q2, xyzA, acc[0][2][zl]);
                acc[0][3][zl] = ffma2(q3, xyzA, acc[0][3][zl]);
                acc[1][0][zl] = ffma2(q0, xyzB, acc[1][0][zl]);
                acc[1][1][zl] = ffma2(q1, xyzB, acc[1][1][zl]);
                acc[1][2][zl] = ffma2(q2, xyzB, acc[1][2][zl]);
                acc[1][3][zl] = ffma2(q3, xyzB, acc[1][3][zl]);
            }
        }
        __syncthreads();
    }

#pragma unroll
    for (int t = 0; t < 2; t++) {
        int iy = iy0 + t;
        if (iy < NM) {
#pragma unroll
            for (int zl = 0; zl < 4; zl++) {
                int z = z0 + zl;
                if (z < NM) {
#pragma unroll
                    for (int c = 0; c < NCH; c++) {
                        g_Fp[(((split*NB + b)*NCH + c)*NXH + ixh)*NPLANE + iy*NM + z] =
                            upk(acc[t][c][zl]);
                    }
                }
            }
        }
    }
}

// ---------------------------------------------------------------------------
// 4b) Reduce partials + fold mult AND Hermitian weight into padded layout
// ---------------------------------------------------------------------------
__global__ void reduce_kernel() {
    int idx = blockIdx.x * blockDim.x + threadIdx.x;
    if (idx >= FPAD) return;
    int z   = idx & 31;
    int iy  = (idx >> 5) & 31;
    int c   = (idx >> 10) & 3;
    int ixh = (idx >> 12) & 15;
    int b   = idx >> 16;
    float2 s = make_float2(0.0f, 0.0f);
    if (z < NM && iy < NM) {
        const int TOT = NB*NCH*NXH*NPLANE;
        int src = (((b)*NCH + c)*NXH + ixh)*NPLANE + iy*NM + z;
#pragma unroll
        for (int sp = 0; sp < NSPLIT; sp++) {
            float2 v = g_Fp[sp*TOT + src];
            s.x += v.x; s.y += v.y;
        }
        float m = g_mult[(15 + ixh)*NPLANE + iy*NM + z];
        if (ixh > 0) m *= 2.0f;              // Hermitian half-space weight
        s.x *= m; s.y *= m;
    }
    g_F2[idx] = s;
}

// ---------------------------------------------------------------------------
// 5) Gather (r6 form, measured ~290 us — NO prefetch; the r13 post-mortem
//    attributes the ~25 us gather regression to the L1-prefetch block
//    competing with the real loads in the L1tex queue). One CTA per
//    (batch, 8 particles); Fr loaded in-loop via coalesced LDG.128 from the
//    padded L2-resident tensor.
// ---------------------------------------------------------------------------
__global__ void __launch_bounds__(256, 2) gather_kernel(const float* __restrict__ charge,
                                                        float* __restrict__ out) {
    const int b   = blockIdx.y;
    const int j0  = blockIdx.x * 8;
    const int tid = threadIdx.x;
    const int iy  = tid >> 3;
    const int zh  = (tid & 7) * 2;       // z0 = zh*2
    const bool act = (iy < NM);
    const int warp = tid >> 5;
    const int lane = tid & 31;

    __shared__ float2     pEx[8][NXH];
    __shared__ float2     pEy[8][32];
    __shared__ ulonglong2 pEz[8][16];    // z pairs, slot z=31 zero
    __shared__ float4     pCh[8];
    __shared__ float      red[8][32];
    __shared__ float      sfin[32];

    u64* pEzU = reinterpret_cast<u64*>(pEz);

    // particle data from g_E3
    for (int idx = tid; idx < 8*32; idx += 256) {
        int p = idx >> 5, i = idx & 31;
        int base = (b*NPTS + j0 + p) * 3;
        pEy[p][i] = g_E3[(base + 1)*32 + i];
        float2 vz = g_E3[(base + 2)*32 + i];
        pEzU[p*32 + i] = pk(vz.x, vz.y);
    }
    if (tid < 8*NXH) {
        int p = tid >> 4, i = tid & 15;
        pEx[p][i] = g_E3[((b*NPTS + j0 + p)*3 + 0)*32 + 15 + i];
    }
    if (tid < 8) {
        pCh[tid] = *reinterpret_cast<const float4*>(&charge[(b*NPTS + j0 + tid)*NCH]);
    }
    __syncthreads();

    u64 acc[8][NCH];
#pragma unroll
    for (int p = 0; p < 8; p++)
#pragma unroll
        for (int c = 0; c < NCH; c++) acc[p][c] = 0ull;

    const ulonglong2* Fbase = reinterpret_cast<const ulonglong2*>(g_F2);

    for (int ixh = 0; ixh < NXH; ixh++) {
        if (act) {
            u64 Fr[NCH][4];
#pragma unroll
            for (int c = 0; c < NCH; c++) {
                const ulonglong2* fp =
                    Fbase + (((b*NXH + ixh)*NCH + c)*32 + iy)*16 + zh;
                ulonglong2 f0 = fp[0];
                ulonglong2 f1 = fp[1];
                Fr[c][0] = f0.x; Fr[c][1] = f0.y;
                Fr[c][2] = f1.x; Fr[c][3] = f1.y;
            }
#pragma unroll
            for (int p = 0; p < 8; p++) {
                float2 exy = cmul(pEx[p][ixh], pEy[p][iy]);
                u64 exq = pk(exy.x, exy.x);
                u64 eyq = pk(-exy.y, exy.y);
                ulonglong2 ez01 = pEz[p][zh];
                ulonglong2 ez23 = pEz[p][zh + 1];
                u64 ezv[4] = {ez01.x, ez01.y, ez23.x, ez23.y};
#pragma unroll
                for (int zl = 0; zl < 4; zl++) {
                    u64 ez = ezv[zl];
                    u64 e2 = ffma2(eyq, swap64(ez), fmul2(exq, ez));   // exy*ez
                    acc[p][0] = ffma2(e2, Fr[0][zl], acc[p][0]);
                    acc[p][1] = ffma2(e2, Fr[1][zl], acc[p][1]);
                    acc[p][2] = ffma2(e2, Fr[2][zl], acc[p][2]);
                    acc[p][3] = ffma2(e2, Fr[3][zl], acc[p][3]);
                }
            }
        }
    }
    __syncthreads();

    // horizontal add (Re part) then block reduction
#pragma unroll
    for (int p = 0; p < 8; p++) {
#pragma unroll
        for (int c = 0; c < NCH; c++) {
            float2 f = upk(acc[p][c]);
            float v = f.x + f.y;
#pragma unroll
            for (int off = 16; off > 0; off >>= 1)
                v += __shfl_xor_sync(0xffffffffu, v, off);
            if (lane == 0) red[warp][p*NCH + c] = v;
        }
    }
    __syncthreads();
    if (tid < 32) {
        float s = 0.0f;
#pragma unroll
        for (int w = 0; w < 8; w++) s += red[w][tid];
        sfin[tid] = s;
    }
    __syncthreads();
    if (tid < 8) {
        float diag = g_diag;
        float4 c4 = pCh[tid];
        float e = c4.x * (sfin[tid*NCH + 0]*INV2V - diag)
                + c4.y * (sfin[tid*NCH + 1]*INV2V - diag)
                + c4.z * (sfin[tid*NCH + 2]*INV2V - diag)
                + c4.w * (sfin[tid*NCH + 3]*INV2V - diag);
        out[b*NPTS + j0 + tid] = e;
    }
}

// ---------------------------------------------------------------------------
// Launch
// ---------------------------------------------------------------------------
extern "C" void kernel_launch(void* const* d_in, const int* in_sizes, int n_in,
                              void* d_out, int out_size) {
    const float* pos    = (const float*)d_in[0];
    const float* charge = (const float*)d_in[1];
    const float* shift  = (const float*)d_in[2];
    const float* amp    = (const float*)d_in[3];
    float* out = (float*)d_out;

    mult_kernel<<<(NK + 255)/256, 256>>>(shift, amp);
    diag_kernel<<<1, 1024>>>();
    etab_kernel<<<(NB*NPTS*32 + 255)/256, 256>>>(pos);
    scatter_kernel<<<dim3(NXH, NB, NSPLIT), 128>>>(charge);
    reduce_kernel<<<(FPAD + 255)/256, 256>>>();
    gather_kernel<<<dim3(NPTS/8, NB), 256>>>(charge, out);
}